// round 12
// baseline (speedup 1.0000x reference)
#include <cuda_runtime.h>
#include <math.h>

#define RBM_B 2048
#define RBM_V 4096
#define RBM_H 1024

// Scratch (device globals: allocation-free rule)
static __device__ float g_WT[(size_t)RBM_H * RBM_V];   // 16 MB  W transposed [H,V]
static __device__ float g_h [(size_t)RBM_B * RBM_H];   //  8 MB  current h
static __device__ float g_v [(size_t)RBM_B * RBM_V];   // 32 MB  current v
static __device__ float g_pos[RBM_B * 16];             // pos partials (16 n-tiles, BN=64)
static __device__ float g_neg[RBM_B * 64];             // neg partials (64 n-tiles, BN=64)

typedef unsigned long long u64;

// packed f32x2 FMA (full-rate fp32 on sm_103a; per-lane rounding == scalar FFMA)
__device__ __forceinline__ void ffma2(u64& d, u64 a, u64 b) {
    asm("fma.rn.f32x2 %0, %1, %2, %0;" : "+l"(d) : "l"(a), "l"(b));
}
__device__ __forceinline__ u64 dup32(float v) {
    unsigned u = __float_as_uint(v);
    return (u64)u | ((u64)u << 32);
}

// ---------------- transpose W[V,H] -> WT[H,V] ----------------
__global__ void k_transpose(const float* __restrict__ W, float* __restrict__ WT) {
    __shared__ float t[32][33];
    int h0 = blockIdx.x * 32, v0 = blockIdx.y * 32;
#pragma unroll
    for (int i = 0; i < 4; ++i)
        t[threadIdx.y + 8*i][threadIdx.x] =
            W[(size_t)(v0 + threadIdx.y + 8*i) * RBM_H + h0 + threadIdx.x];
    __syncthreads();
#pragma unroll
    for (int i = 0; i < 4; ++i)
        WT[(size_t)(h0 + threadIdx.y + 8*i) * RBM_V + v0 + threadIdx.x] =
            t[threadIdx.x][threadIdx.y + 8*i];
}

// ======================= H-output GEMM: 256 threads, 4m x 8n =======================
// C[M,N] = A[M,K] * Bm[K,N]; strict ascending-k fma.rn.f32x2 chain per element
// (bit-identical logits). BM=128, BN=64, BK=16, grid (N/64, M/128) = 256 CTAs.
// Permuted As: u64 index j = r*64 + ty*2 + h <-> row m = ty*4 + 2r + h (ty 0..31),
// so each warp's A-read (ulonglong2 at r*64 + ty*2) is 64B-contiguous: 1 wavefront.
template<int SCORE>
__global__ __launch_bounds__(256, 2)
void k_gemm_h(const float* __restrict__ A, const float* __restrict__ Bm,
              const float* __restrict__ bias, const float* __restrict__ U,
              float* __restrict__ Out, float* __restrict__ Score,
              int K, int N)
{
    constexpr int BM = 128, BN = 64, BK = 16;
    __shared__ __align__(16) u64   As[2][BK][BM];      // dup-A, permuted: 32 KB
    __shared__ __align__(16) float Bs[2][BK][BN];      // plain B: 8 KB

    const int tid = threadIdx.x;
    const int tx = tid & 7, ty = tid >> 3;             // 8 n-octets x 32 m-groups
    const int m0 = blockIdx.y * BM, n0 = blockIdx.x * BN;

    // A loader: thread stores 8 consecutive k at column j = tid>>1, kc = (tid&1)*8.
    // Row for column j (permute inverse): m = ((j&63)>>1)*4 + (j>>6)*2 + (j&1).
    const int aj = tid >> 1, akc = (tid & 1) * 8;
    const int arow = ((aj & 63) >> 1) * 4 + (aj >> 6) * 2 + (aj & 1);
    const float* Aload = A + (size_t)(m0 + arow) * K + akc;
    // B loader: 16 rows x 64 floats = 1 float4 per thread.
    const int brow = tid >> 4, bcol = (tid & 15) * 4;
    const float* Bload = Bm + (size_t)brow * N + n0 + bcol;

    // acc[mr 0..3][j 0..3]: u64 = fp32 pair, cols ((j>>1)*32 + tx*4 + 2*(j&1), +1)
    u64 acc[4][4];
#pragma unroll
    for (int m = 0; m < 4; ++m)
#pragma unroll
        for (int j = 0; j < 4; ++j) acc[m][j] = 0ull;

    float4 pa[2], pb;

    // ---- prologue: tile 0 ----
    pa[0] = *(const float4*)(Aload);
    pa[1] = *(const float4*)(Aload + 4);
    pb    = *(const float4*)(Bload);
#pragma unroll
    for (int c = 0; c < 8; ++c)
        As[0][akc + c][aj] = dup32(((const float*)&pa[0])[c]);
    *(float4*)&Bs[0][brow][bcol] = pb;
    __syncthreads();

    const int nk = K / BK;
    int buf = 0;
    for (int t = 0; t < nk; ++t) {
        if (t + 1 < nk) {
            const float* Ap = Aload + (t + 1) * BK;
            pa[0] = *(const float4*)(Ap);
            pa[1] = *(const float4*)(Ap + 4);
            pb    = *(const float4*)(Bload + (size_t)(t + 1) * BK * N);
        }
#pragma unroll
        for (int kk = 0; kk < BK; ++kk) {
            u64 ap[4];
#pragma unroll
            for (int r = 0; r < 2; ++r) {
                ulonglong2 a2 = *(const ulonglong2*)&As[buf][kk][r * 64 + ty * 2];
                ap[r * 2] = a2.x; ap[r * 2 + 1] = a2.y;
            }
            u64 bp[4];
#pragma unroll
            for (int q = 0; q < 2; ++q) {
                ulonglong2 b2 = *(const ulonglong2*)&Bs[buf][kk][q * 32 + tx * 4];
                bp[q * 2] = b2.x; bp[q * 2 + 1] = b2.y;
            }
#pragma unroll
            for (int m = 0; m < 4; ++m)
#pragma unroll
                for (int j = 0; j < 4; ++j)
                    ffma2(acc[m][j], ap[m], bp[j]);
        }
        if (t + 1 < nk) {
            int nb = buf ^ 1;
#pragma unroll
            for (int c = 0; c < 8; ++c)
                As[nb][akc + c][aj] = dup32(((const float*)&pa[0])[c]);
            *(float4*)&Bs[nb][brow][bcol] = pb;
        }
        __syncthreads();
        buf ^= 1;
    }

    // ---- epilogue ----
    float biasv[8];
#pragma unroll
    for (int q = 0; q < 2; ++q)
        *(float4*)&biasv[q * 4] = *(const float4*)(bias + n0 + q * 32 + tx * 4);
#pragma unroll
    for (int m = 0; m < 4; ++m) {
        int gm = m0 + ty * 4 + m;
        float sp = 0.f;
#pragma unroll
        for (int q = 0; q < 2; ++q) {
            int gn = n0 + q * 32 + tx * 4;
            float4 u4 = *(const float4*)(U + (size_t)gm * N + gn);
            float2 e0 = *(float2*)&acc[m][q * 2];
            float2 e1 = *(float2*)&acc[m][q * 2 + 1];
            float l[4] = { e0.x + biasv[q*4],   e0.y + biasv[q*4+1],
                           e1.x + biasv[q*4+2], e1.y + biasv[q*4+3] };
            float s[4];
#pragma unroll
            for (int j = 0; j < 4; ++j) {
                float pr = 1.0f / (1.0f + expf(-l[j]));
                s[j] = (pr > ((const float*)&u4)[j]) ? 1.0f : 0.0f;
            }
            *(float4*)(Out + (size_t)gm * N + gn) = make_float4(s[0], s[1], s[2], s[3]);
            if (SCORE) sp += s[0]*l[0] + s[1]*l[1] + s[2]*l[2] + s[3]*l[3];
        }
        if (SCORE) {
            sp += __shfl_xor_sync(0xffffffffu, sp, 1);
            sp += __shfl_xor_sync(0xffffffffu, sp, 2);
            sp += __shfl_xor_sync(0xffffffffu, sp, 4);
            if (tx == 0) Score[(size_t)gm * gridDim.x + blockIdx.x] = sp;
        }
    }
}

// ======================= V-output GEMM: 128 threads, 8m x 8n (r11 body) ============
template<int SCORE>
__global__ __launch_bounds__(128, 3)
void k_gemm_v(const float* __restrict__ A, const float* __restrict__ Bm,
              const float* __restrict__ bias, const float* __restrict__ U,
              float* __restrict__ Out, float* __restrict__ Score,
              int K, int N)
{
    constexpr int BM = 128, BN = 64, BK = 16;
    __shared__ __align__(16) u64   As[2][BK][BM];
    __shared__ __align__(16) float Bs[2][BK][BN];

    const int tid = threadIdx.x;
    const int tx = tid & 7, ty = tid >> 3;
    const int m0 = blockIdx.y * BM, n0 = blockIdx.x * BN;

    const int arow = ((tid >> 1) & 15) * 8 + (tid >> 5) * 2 + (tid & 1);
    const float* Aload = A + (size_t)(m0 + arow) * K;
    const int brow = tid >> 3, bcol = (tid & 7) * 8;
    const float* Bload = Bm + (size_t)brow * N + n0 + bcol;

    u64 acc[8][4];
#pragma unroll
    for (int m = 0; m < 8; ++m)
#pragma unroll
        for (int j = 0; j < 4; ++j) acc[m][j] = 0ull;

    float4 pa[4], pb[2];

#pragma unroll
    for (int q = 0; q < 4; ++q) pa[q] = *(const float4*)(Aload + q * 4);
#pragma unroll
    for (int q = 0; q < 2; ++q) pb[q] = *(const float4*)(Bload + q * 4);
#pragma unroll
    for (int c = 0; c < 16; ++c)
        As[0][c][tid] = dup32(((const float*)&pa[0])[c]);
#pragma unroll
    for (int q = 0; q < 2; ++q)
        *(float4*)&Bs[0][brow][bcol + q * 4] = pb[q];
    __syncthreads();

    const int nk = K / BK;
    int buf = 0;
    for (int t = 0; t < nk; ++t) {
        if (t + 1 < nk) {
            const float* Ap = Aload + (t + 1) * BK;
            const float* Bp = Bload + (size_t)(t + 1) * BK * N;
#pragma unroll
            for (int q = 0; q < 4; ++q) pa[q] = *(const float4*)(Ap + q * 4);
#pragma unroll
            for (int q = 0; q < 2; ++q) pb[q] = *(const float4*)(Bp + q * 4);
        }
#pragma unroll
        for (int kk = 0; kk < BK; ++kk) {
            u64 ap[8];
#pragma unroll
            for (int q = 0; q < 4; ++q) {
                ulonglong2 a2 = *(const ulonglong2*)&As[buf][kk][q * 32 + ty * 2];
                ap[q * 2] = a2.x; ap[q * 2 + 1] = a2.y;
            }
            u64 bp[4];
#pragma unroll
            for (int q = 0; q < 2; ++q) {
                ulonglong2 b2 = *(const ulonglong2*)&Bs[buf][kk][q * 32 + tx * 4];
                bp[q * 2] = b2.x; bp[q * 2 + 1] = b2.y;
            }
#pragma unroll
            for (int m = 0; m < 8; ++m)
#pragma unroll
                for (int j = 0; j < 4; ++j)
                    ffma2(acc[m][j], ap[m], bp[j]);
        }
        if (t + 1 < nk) {
            int nb = buf ^ 1;
#pragma unroll
            for (int c = 0; c < 16; ++c)
                As[nb][c][tid] = dup32(((const float*)&pa[0])[c]);
#pragma unroll
            for (int q = 0; q < 2; ++q)
                *(float4*)&Bs[nb][brow][bcol + q * 4] = pb[q];
        }
        __syncthreads();
        buf ^= 1;
    }

    float biasv[8];
#pragma unroll
    for (int q = 0; q < 2; ++q)
        *(float4*)&biasv[q * 4] = *(const float4*)(bias + n0 + q * 32 + tx * 4);
#pragma unroll
    for (int m = 0; m < 8; ++m) {
        int gm = m0 + ty * 8 + m;
        float sp = 0.f;
#pragma unroll
        for (int q = 0; q < 2; ++q) {
            int gn = n0 + q * 32 + tx * 4;
            float4 u4 = *(const float4*)(U + (size_t)gm * N + gn);
            float2 e0 = *(float2*)&acc[m][q * 2];
            float2 e1 = *(float2*)&acc[m][q * 2 + 1];
            float l[4] = { e0.x + biasv[q*4],   e0.y + biasv[q*4+1],
                           e1.x + biasv[q*4+2], e1.y + biasv[q*4+3] };
            float s[4];
#pragma unroll
            for (int j = 0; j < 4; ++j) {
                float pr = 1.0f / (1.0f + expf(-l[j]));
                s[j] = (pr > ((const float*)&u4)[j]) ? 1.0f : 0.0f;
            }
            *(float4*)(Out + (size_t)gm * N + gn) = make_float4(s[0], s[1], s[2], s[3]);
            if (SCORE) sp += s[0]*l[0] + s[1]*l[1] + s[2]*l[2] + s[3]*l[3];
        }
        if (SCORE) {
            sp += __shfl_xor_sync(0xffffffffu, sp, 1);
            sp += __shfl_xor_sync(0xffffffffu, sp, 2);
            sp += __shfl_xor_sync(0xffffffffu, sp, 4);
            if (tx == 0) Score[(size_t)gm * gridDim.x + blockIdx.x] = sp;
        }
    }
}

// ---------------- finalize: out[b] = (v.b_v + pos) - (neg + h2.b_h) ----------------
__global__ void k_finalize(const float* __restrict__ visible, const float* __restrict__ b_v,
                           const float* __restrict__ b_h, float* __restrict__ out)
{
    int b = blockIdx.x, tid = threadIdx.x;
    float acc = 0.f;
    const float* vr = visible + (size_t)b * RBM_V;
    for (int i = tid; i < RBM_V; i += 256) acc += vr[i] * b_v[i];
    const float* hr = g_h + (size_t)b * RBM_H;            // g_h holds h2 here
    for (int i = tid; i < RBM_H; i += 256) acc -= hr[i] * b_h[i];
    if (tid < 16) acc += g_pos[b * 16 + tid];             // 16 n-tiles (N=1024, BN=64)
    if (tid < 64) acc -= g_neg[b * 64 + tid];             // 64 n-tiles (N=4096, BN=64)
    __shared__ float red[256];
    red[tid] = acc;
    __syncthreads();
    for (int o = 128; o; o >>= 1) { if (tid < o) red[tid] += red[tid + o]; __syncthreads(); }
    if (tid == 0) out[b] = red[0];
}

// ---------------- launch ----------------
extern "C" void kernel_launch(void* const* d_in, const int* in_sizes, int n_in,
                              void* d_out, int out_size)
{
    const float* visible = (const float*)d_in[0];
    const float* b_v     = (const float*)d_in[1];
    const float* b_h     = (const float*)d_in[2];
    const float* W       = (const float*)d_in[3];
    const float* u_h0    = (const float*)d_in[4];
    const float* u_v     = (const float*)d_in[5];
    const float* u_h     = (const float*)d_in[6];
    float* out = (float*)d_out;

    float *WT, *hb, *vb, *pos, *neg;
    cudaGetSymbolAddress((void**)&WT,  g_WT);
    cudaGetSymbolAddress((void**)&hb,  g_h);
    cudaGetSymbolAddress((void**)&vb,  g_v);
    cudaGetSymbolAddress((void**)&pos, g_pos);
    cudaGetSymbolAddress((void**)&neg, g_neg);

    k_transpose<<<dim3(RBM_H / 32, RBM_V / 32), dim3(32, 8)>>>(W, WT);

    dim3 gH(RBM_H / 64, RBM_B / 128);   // (16, 16) = 256 CTAs, 256 threads
    dim3 gV(RBM_V / 64, RBM_B / 128);   // (64, 16) = 1024 CTAs, 128 threads

    const size_t BV = (size_t)RBM_B * RBM_V;
    const size_t BH = (size_t)RBM_B * RBM_H;

    // positive phase: h0 | data, fused pos-score
    k_gemm_h<1><<<gH, 256>>>(visible, W,  b_h, u_h0,        hb, pos,    RBM_V, RBM_H);
    // Gibbs chain: v,h,v,h,v
    k_gemm_v<0><<<gV, 128>>>(hb,      WT, b_v, u_v + 0*BV,  vb, nullptr, RBM_H, RBM_V);
    k_gemm_h<0><<<gH, 256>>>(vb,      W,  b_h, u_h + 0*BH,  hb, nullptr, RBM_V, RBM_H);
    k_gemm_v<0><<<gV, 128>>>(hb,      WT, b_v, u_v + 1*BV,  vb, nullptr, RBM_H, RBM_V);
    k_gemm_h<0><<<gH, 256>>>(vb,      W,  b_h, u_h + 1*BH,  hb, nullptr, RBM_V, RBM_H);
    // last v-step: fused neg-score
    k_gemm_v<2><<<gV, 128>>>(hb,      WT, b_v, u_v + 2*BV,  vb, neg,     RBM_H, RBM_V);

    k_finalize<<<RBM_B, 256>>>(visible, b_v, b_h, out);
}